// round 12
// baseline (speedup 1.0000x reference)
// Round 12: resubmission of round-11 source (round 11 hit the GB300 broker
// infra failure twice; kernel never compiled/ran). Under test: GEMM v2 with
// 512 threads (4 warps/SMSP), 128x256 tile, BK=32, merged transconv.
#include <cuda_runtime.h>
#include <math.h>

#define B_   2
#define S_   2048
#define D_   2048
#define H_   16
#define DH_  128
#define P_   16
#define SP_  2064
#define BS_  4096
#define EPS_ 1e-5f

// ---------------- static scratch ----------------
__device__ __align__(16) unsigned short g_A1h[BS_ * D_];
__device__ __align__(16) unsigned short g_A1l[BS_ * D_];
__device__ __align__(16) unsigned short g_Bqh[3 * D_ * D_];
__device__ __align__(16) unsigned short g_Bql[3 * D_ * D_];
__device__ __align__(16) unsigned short g_Boh[D_ * D_];
__device__ __align__(16) unsigned short g_Bol[D_ * D_];
__device__ __align__(16) unsigned short g_A2h[BS_ * D_];
__device__ __align__(16) unsigned short g_A2l[BS_ * D_];
__device__ float g_mix[BS_ * H_];
__device__ __align__(16) unsigned short g_qh[B_ * H_ * S_  * DH_];
__device__ __align__(16) unsigned short g_ql[B_ * H_ * S_  * DH_];
__device__ __align__(16) unsigned short g_kh[B_ * H_ * SP_ * DH_];
__device__ __align__(16) unsigned short g_kl[B_ * H_ * SP_ * DH_];
__device__ __align__(16) unsigned short g_vh[B_ * H_ * SP_ * DH_];
__device__ __align__(16) unsigned short g_vl[B_ * H_ * SP_ * DH_];

// ---------------- helpers ----------------
__device__ __forceinline__ unsigned smem_u32(const void* p) {
    unsigned a;
    asm("{ .reg .u64 t; cvta.to.shared.u64 t, %1; cvt.u32.u64 %0, t; }" : "=r"(a) : "l"(p));
    return a;
}
__device__ __forceinline__ void cp16(unsigned s, const void* g) {
    asm volatile("cp.async.cg.shared.global [%0], [%1], 16;" :: "r"(s), "l"(g));
}
#define CP_COMMIT() asm volatile("cp.async.commit_group;" ::: "memory")
#define CP_WAIT1()  asm volatile("cp.async.wait_group 1;" ::: "memory")
#define CP_WAIT0()  asm volatile("cp.async.wait_group 0;" ::: "memory")

#define LDM4(d0, d1, d2, d3, addr) \
    asm volatile("ldmatrix.sync.aligned.m8n8.x4.shared.b16 {%0,%1,%2,%3}, [%4];" \
        : "=r"(d0), "=r"(d1), "=r"(d2), "=r"(d3) : "r"(addr))
#define LDM4T(d0, d1, d2, d3, addr) \
    asm volatile("ldmatrix.sync.aligned.m8n8.x4.trans.shared.b16 {%0,%1,%2,%3}, [%4];" \
        : "=r"(d0), "=r"(d1), "=r"(d2), "=r"(d3) : "r"(addr))

#define MMA_BF16(c0, c1, c2, c3, a0, a1, a2, a3, b0, b1) \
    asm volatile("mma.sync.aligned.m16n8k16.row.col.f32.bf16.bf16.f32 " \
        "{%0,%1,%2,%3}, {%4,%5,%6,%7}, {%8,%9}, {%0,%1,%2,%3};" \
        : "+f"(c0), "+f"(c1), "+f"(c2), "+f"(c3) \
        : "r"(a0), "r"(a1), "r"(a2), "r"(a3), "r"(b0), "r"(b1))

// 64-byte-row swizzle (GEMM tiles, BK=32)
__device__ __forceinline__ unsigned swz(unsigned off) {
    return off ^ (((off >> 7) & 3u) << 4);
}

// bf16 split, RNE, scalar
#define SPLIT2(v, hb, lb) do { \
    float _v = (v); \
    unsigned _u = __float_as_uint(_v); \
    hb = (_u + 0x7FFFu + ((_u >> 16) & 1u)) >> 16; \
    float _r = _v - __uint_as_float(hb << 16); \
    unsigned _w = __float_as_uint(_r); \
    lb = (_w + 0x7FFFu + ((_w >> 16) & 1u)) >> 16; \
} while (0)

// paired split via cvt.rn.bf16x2
#define SPLIT2X2(v0, v1, hpack, lpack) do { \
    float _a = (v0), _b = (v1); \
    asm("cvt.rn.bf16x2.f32 %0, %1, %2;" : "=r"(hpack) : "f"(_b), "f"(_a)); \
    float _r0 = _a - __uint_as_float((hpack) << 16); \
    float _r1 = _b - __uint_as_float((hpack) & 0xFFFF0000u); \
    asm("cvt.rn.bf16x2.f32 %0, %1, %2;" : "=r"(lpack) : "f"(_r1), "f"(_r0)); \
} while (0)

// ---------------- kernel 1: LayerNorm + mix gate + bf16 split ----------------
__global__ __launch_bounds__(256) void ln_mix_kernel(
    const float* __restrict__ x, const float* __restrict__ lng,
    const float* __restrict__ lnb, const float* __restrict__ wmix,
    const float* __restrict__ bmix)
{
    int row = blockIdx.x;
    int tid = threadIdx.x;
    const float4* x4 = (const float4*)(x + (size_t)row * D_);
    float4 v0 = x4[tid];
    float4 v1 = x4[tid + 256];

    float s  = v0.x + v0.y + v0.z + v0.w + v1.x + v1.y + v1.z + v1.w;
    float s2 = v0.x*v0.x + v0.y*v0.y + v0.z*v0.z + v0.w*v0.w
             + v1.x*v1.x + v1.y*v1.y + v1.z*v1.z + v1.w*v1.w;
    #pragma unroll
    for (int o = 16; o; o >>= 1) {
        s  += __shfl_xor_sync(0xffffffffu, s,  o);
        s2 += __shfl_xor_sync(0xffffffffu, s2, o);
    }
    __shared__ float rs[8], rs2[8];
    int warp = tid >> 5, lane = tid & 31;
    if (lane == 0) { rs[warp] = s; rs2[warp] = s2; }
    __syncthreads();
    if (tid == 0) {
        float a = 0.f, b2 = 0.f;
        for (int w = 0; w < 8; w++) { a += rs[w]; b2 += rs2[w]; }
        rs[0] = a; rs2[0] = b2;
    }
    __syncthreads();
    float mu   = rs[0]  * (1.0f / D_);
    float var  = rs2[0] * (1.0f / D_) - mu * mu;
    float rstd = rsqrtf(var + EPS_);

    float xn[8];
    float xv[8] = {v0.x, v0.y, v0.z, v0.w, v1.x, v1.y, v1.z, v1.w};
    int jidx[8];
    #pragma unroll
    for (int e = 0; e < 8; e++) {
        int j = (e < 4) ? (4 * tid + e) : (1024 + 4 * tid + (e - 4));
        jidx[e] = j;
        xn[e] = (xv[e] - mu) * rstd * lng[j] + lnb[j];
    }
    unsigned hb[8], lb[8];
    #pragma unroll
    for (int e = 0; e < 8; e++) SPLIT2(xn[e], hb[e], lb[e]);
    size_t base = (size_t)row * D_;
    *(uint2*)(g_A1h + base + 4 * tid) =
        make_uint2(hb[0] | (hb[1] << 16), hb[2] | (hb[3] << 16));
    *(uint2*)(g_A1l + base + 4 * tid) =
        make_uint2(lb[0] | (lb[1] << 16), lb[2] | (lb[3] << 16));
    *(uint2*)(g_A1h + base + 1024 + 4 * tid) =
        make_uint2(hb[4] | (hb[5] << 16), hb[6] | (hb[7] << 16));
    *(uint2*)(g_A1l + base + 1024 + 4 * tid) =
        make_uint2(lb[4] | (lb[5] << 16), lb[6] | (lb[7] << 16));

    float acc[16];
    #pragma unroll
    for (int h = 0; h < 16; h++) acc[h] = 0.f;
    #pragma unroll
    for (int e = 0; e < 8; e++) {
        const float4* wm = (const float4*)(wmix + (size_t)jidx[e] * H_);
        float4 a0 = wm[0], a1 = wm[1], a2 = wm[2], a3 = wm[3];
        float xe = xn[e];
        acc[0]  += xe * a0.x; acc[1]  += xe * a0.y; acc[2]  += xe * a0.z; acc[3]  += xe * a0.w;
        acc[4]  += xe * a1.x; acc[5]  += xe * a1.y; acc[6]  += xe * a1.z; acc[7]  += xe * a1.w;
        acc[8]  += xe * a2.x; acc[9]  += xe * a2.y; acc[10] += xe * a2.z; acc[11] += xe * a2.w;
        acc[12] += xe * a3.x; acc[13] += xe * a3.y; acc[14] += xe * a3.z; acc[15] += xe * a3.w;
    }
    #pragma unroll
    for (int h = 0; h < 16; h++) {
        #pragma unroll
        for (int o = 16; o; o >>= 1) acc[h] += __shfl_xor_sync(0xffffffffu, acc[h], o);
    }
    __shared__ float wsum[8][16];
    if (lane == 0) {
        #pragma unroll
        for (int h = 0; h < 16; h++) wsum[warp][h] = acc[h];
    }
    __syncthreads();
    if (tid < 16) {
        float t = 0.f;
        #pragma unroll
        for (int w = 0; w < 8; w++) t += wsum[w][tid];
        t += bmix[tid];
        g_mix[(size_t)row * H_ + tid] = 1.0f / (1.0f + expf(-t));
    }
}

// ---------------- merged transpose + split of both weight matrices ----------
__global__ __launch_bounds__(256) void transconv_kernel(
    const float* __restrict__ wqkv, const float* __restrict__ wout)
{
    const float* src;
    unsigned short* dhi;
    unsigned short* dlo;
    int Cols, bxe;
    int bx = blockIdx.x;
    if (bx < 192) { src = wqkv; dhi = g_Bqh; dlo = g_Bql; Cols = 3 * D_; bxe = bx; }
    else          { src = wout; dhi = g_Boh; dlo = g_Bol; Cols = D_;     bxe = bx - 192; }
    const int Rows = D_;

    __shared__ float tile[32][33];
    int bcol = bxe * 32;
    int brow = blockIdx.y * 32;
    int tx = threadIdx.x & 31, ty = threadIdx.x >> 5;
    #pragma unroll
    for (int i = 0; i < 32; i += 8)
        tile[ty + i][tx] = src[(size_t)(brow + ty + i) * Cols + bcol + tx];
    __syncthreads();
    #pragma unroll
    for (int i = 0; i < 32; i += 8) {
        unsigned h, l;
        SPLIT2(tile[tx][ty + i], h, l);
        size_t o = (size_t)(bcol + ty + i) * Rows + brow + tx;
        dhi[o] = (unsigned short)h;
        dlo[o] = (unsigned short)l;
    }
}

// ---------------- pmem prepend (split bf16) ----------------
__global__ __launch_bounds__(256) void pmem_kernel(const float* __restrict__ pmem)
{
    int i = blockIdx.x * 256 + threadIdx.x;
    int b = i >> 15;
    int rem = i & 32767;
    int h = rem >> 11;
    int jd = rem & 2047;
    int j = jd >> 7, d = jd & 127;
    size_t dst = (((size_t)(b * H_ + h)) * SP_ + j) * DH_ + d;
    unsigned kh, kl, vh, vl;
    SPLIT2(pmem[rem], kh, kl);
    SPLIT2(pmem[32768 + rem], vh, vl);
    g_kh[dst] = (unsigned short)kh;
    g_kl[dst] = (unsigned short)kl;
    g_vh[dst] = (unsigned short)vh;
    g_vl[dst] = (unsigned short)vl;
}

// ---------------- HMMA bf16x3 GEMM v2: 128x256 tile, 512 thr, BK=32, 3-stage -
#define BK_ 32
#define NCH (D_ / BK_)          // 64 chunks
#define STG 49152               // Ah 8K | Al 8K | Bh 16K | Bl 16K
#define GEMM_SMEM (3 * STG + 1024)

// 512 threads: A chunk ids = tid (128 rows x 4 c); B chunk ids = tid, tid+512
#define LOAD_STAGE(st, k0) do { \
    unsigned _sp = sbase + (st) * STG; \
    { \
        int _r = tid >> 2, _c = tid & 3; \
        unsigned _sw = swz((unsigned)(_r * 64 + _c * 16)); \
        size_t _ga = (size_t)(m0 + _r) * D_ + (k0) + _c * 8; \
        cp16(_sp + _sw,        Ah + _ga); \
        cp16(_sp + 8192 + _sw, Al + _ga); \
    } \
    _Pragma("unroll") \
    for (int _i = 0; _i < 2; _i++) { \
        int _ci = tid + _i * 512; \
        int _r = _ci >> 2, _c = _ci & 3; \
        unsigned _sw = swz((unsigned)(_r * 64 + _c * 16)); \
        size_t _gb = (size_t)(n0 + _r) * D_ + (k0) + _c * 8; \
        cp16(_sp + 16384 + _sw, Bh + _gb); \
        cp16(_sp + 32768 + _sw, Bl + _gb); \
    } \
} while (0)

template <int MODE>
__global__ __launch_bounds__(512, 1) void gemm_kernel(
    const float* __restrict__ vres, const float* __restrict__ bout,
    float* __restrict__ Cout)
{
    extern __shared__ char dynsm[];
    unsigned braw = smem_u32(dynsm);
    unsigned sbase = (braw + 1023) & ~1023u;

    int tid = threadIdx.x;
    int lane = tid & 31, wid = tid >> 5;
    int warp_m = wid & 3, warp_n = wid >> 2;
    int m0 = blockIdx.y * 128, n0 = blockIdx.x * 256;
    int wm = warp_m * 32, wn = warp_n * 64;

    const unsigned short* Ah = (MODE == 0) ? g_A1h : g_A2h;
    const unsigned short* Al = (MODE == 0) ? g_A1l : g_A2l;
    const unsigned short* Bh = (MODE == 0) ? g_Bqh : g_Boh;
    const unsigned short* Bl = (MODE == 0) ? g_Bql : g_Bol;

    int t4 = lane >> 3, lr = lane & 7;
    int a_row = ((t4 & 1) << 3) + lr;
    int a_cb  = (t4 >> 1) << 4;
    int b_row = ((t4 >> 1) << 3) + lr;
    int b_cb  = (t4 & 1) << 4;

    float acc[2][8][4];
    #pragma unroll
    for (int i = 0; i < 2; i++)
        #pragma unroll
        for (int j = 0; j < 8; j++)
            #pragma unroll
            for (int q = 0; q < 4; q++) acc[i][j][q] = 0.f;

    LOAD_STAGE(0, 0); CP_COMMIT();
    LOAD_STAGE(1, BK_); CP_COMMIT();

    #pragma unroll 1
    for (int c = 0; c < NCH; c++) {
        if (c + 2 < NCH) CP_WAIT1(); else CP_WAIT0();
        __syncthreads();
        if (c + 2 < NCH) { LOAD_STAGE((c + 2) % 3, (c + 2) * BK_); CP_COMMIT(); }

        unsigned sp = sbase + (c % 3) * STG;
        unsigned sAh = sp, sAl = sp + 8192, sBh = sp + 16384, sBl = sp + 32768;

        #pragma unroll
        for (int ks = 0; ks < 2; ks++) {
            unsigned bh[8][2], bl[8][2];
            #pragma unroll
            for (int np = 0; np < 4; np++) {
                unsigned off = swz((unsigned)((wn + np * 16 + b_row) * 64 + ks * 32 + b_cb));
                LDM4(bh[2*np][0], bh[2*np][1], bh[2*np+1][0], bh[2*np+1][1], sBh + off);
                LDM4(bl[2*np][0], bl[2*np][1], bl[2*np+1][0], bl[2*np+1][1], sBl + off);
            }
            #pragma unroll
            for (int mt = 0; mt < 2; mt++) {
                unsigned ah0, ah1, ah2, ah3, al0, al1, al2, al3;
                unsigned off = swz((unsigned)((wm + mt * 16 + a_row) * 64 + ks * 32 + a_cb));
                LDM4(ah0, ah1, ah2, ah3, sAh + off);
                LDM4(al0, al1, al2, al3, sAl + off);
                #pragma unroll
                for (int nt = 0; nt < 8; nt++) {
                    MMA_BF16(acc[mt][nt][0], acc[mt][nt][1], acc[mt][nt][2], acc[mt][nt][3],
                             ah0, ah1, ah2, ah3, bh[nt][0], bh[nt][1]);
                    MMA_BF16(acc[mt][nt][0], acc[mt][nt][1], acc[mt][nt][2], acc[mt][nt][3],
                             ah0, ah1, ah2, ah3, bl[nt][0], bl[nt][1]);
                    MMA_BF16(acc[mt][nt][0], acc[mt][nt][1], acc[mt][nt][2], acc[mt][nt][3],
                             al0, al1, al2, al3, bh[nt][0], bh[nt][1]);
                }
            }
        }
        __syncthreads();
    }

    // ---- epilogue ----
    #pragma unroll
    for (int mt = 0; mt < 2; mt++) {
        #pragma unroll
        for (int nt = 0; nt < 8; nt++) {
            int mrow0 = m0 + wm + mt * 16 + (lane >> 2);
            int n     = n0 + wn + nt * 8 + 2 * (lane & 3);
            #pragma unroll
            for (int half = 0; half < 2; half++) {
                int m = mrow0 + half * 8;
                float va = acc[mt][nt][2 * half];
                float vb = acc[mt][nt][2 * half + 1];
                int b = m >> 11, sg = m & 2047;
                if (MODE == 0) {
                    int seg = n >> 11;
                    int nn = n & 2047;
                    int hd = nn >> 7, d = nn & 127;
                    if (seg == 2) {
                        float mx = g_mix[(size_t)m * H_ + hd];
                        float2 vr = *(const float2*)(vres + (((size_t)(b * H_ + hd)) * S_ + sg) * DH_ + d);
                        float om = 1.0f - mx;
                        va = va * om + vr.x * mx;
                        vb = vb * om + vr.y * mx;
                    }
                    unsigned hp, lp;
                    SPLIT2X2(va, vb, hp, lp);
                    if (seg == 0) {
                        size_t idx = (((size_t)(b * H_ + hd)) * S_ + sg) * DH_ + d;
                        *(unsigned*)(g_qh + idx) = hp;
                        *(unsigned*)(g_ql + idx) = lp;
                    } else if (seg == 1) {
                        size_t idx = (((size_t)(b * H_ + hd)) * SP_ + P_ + sg) * DH_ + d;
                        *(unsigned*)(g_kh + idx) = hp;
                        *(unsigned*)(g_kl + idx) = lp;
                    } else {
                        size_t idx = (((size_t)(b * H_ + hd)) * SP_ + P_ + sg) * DH_ + d;
                        *(unsigned*)(g_vh + idx) = hp;
                        *(unsigned*)(g_vl + idx) = lp;
                    }
                } else {
                    *(float2*)(Cout + (size_t)m * D_ + n) =
                        make_float2(va + bout[n], vb + bout[n + 1]);
                }
            }
        }
    }
}

// ---------------- flash attention v3 (unchanged from round 10) ---------------
#define AQH 0
#define AQL 32768
#define AKV0 65536
#define ATTN_SMEM (196608 + 1024)

#define LOAD_KV(bufi, j0v) do { \
    unsigned _kb = sbase + AKV0 + (bufi) * 65536; \
    size_t _gk = (size_t)bh * SP_; \
    _Pragma("unroll") \
    for (int _i = 0; _i < 4; _i++) { \
        int _ci = tid + _i * 256; \
        int _r = _ci >> 4, _c = _ci & 15; \
        int _jg = (j0v) + _r; if (_jg > SP_ - 1) _jg = SP_ - 1; \
        unsigned _d = _kb + (unsigned)(_r * 256) + (((unsigned)_c ^ ((unsigned)_r & 7u)) << 4); \
        size_t _go = (_gk + _jg) * DH_ + _c * 8; \
        cp16(_d,         g_kh + _go); \
        cp16(_d + 16384, g_kl + _go); \
        cp16(_d + 32768, g_vh + _go); \
        cp16(_d + 49152, g_vl + _go); \
    } \
} while (0)

__global__ __launch_bounds__(256, 1) void attn_kernel()
{
    extern __shared__ char dynsm2[];
    unsigned braw = smem_u32(dynsm2);
    unsigned sbase = (braw + 1023) & ~1023u;

    int tid = threadIdx.x;
    int lane = tid & 31, wid = tid >> 5;
    int qt = blockIdx.x, h = blockIdx.y, b = blockIdx.z;
    int bh = b * H_ + h;
    int qbase = qt * 128;

    {
        size_t gq = (size_t)bh * S_ + qbase;
        #pragma unroll
        for (int i = 0; i < 8; i++) {
            int ci = tid + i * 256;
            int r = ci >> 4, c = ci & 15;
            unsigned dst = sbase + AQH + (unsigned)(r * 256) + (((unsigned)c ^ ((unsigned)r & 7u)) << 4);
            cp16(dst,         g_qh + (gq + r) * DH_ + c * 8);
            cp16(dst + 32768, g_ql + (gq + r) * DH_ + c * 8);
        }
    }
    LOAD_KV(0, 0);
    CP_COMMIT();

    float oacc[16][4];
    #pragma unroll
    for (int i = 0; i < 16; i++)
        #pragma unroll
        for (int q = 0; q < 4; q++) oacc[i][q] = 0.f;
    float mrow0 = -INFINITY, mrow1 = -INFINITY, lrow0 = 0.f, lrow1 = 0.f;

    const float scale = 0.08838834764831845f;
    int ntiles = (P_ + qbase + 128 + 63) >> 6;

    int t4 = lane >> 3, lr = lane & 7;
    int a_row  = ((t4 & 1) << 3) + lr;
    int a_csel = t4 >> 1;
    int b_row  = ((t4 >> 1) << 3) + lr;
    int b_csel = t4 & 1;
    int r_b = lane >> 2, c_b = (lane & 3) * 2;
    int wmQ = wid * 16;
    int ig0 = qbase + wmQ + r_b;
    int ig1 = ig0 + 8;

    #pragma unroll 1
    for (int t = 0; t < ntiles; t++) {
        int j0 = t << 6;
        if (t + 1 < ntiles) { LOAD_KV((t + 1) & 1, (t + 1) * 64); CP_COMMIT(); CP_WAIT1(); }
        else CP_WAIT0();
        __syncthreads();

        unsigned kvb = sbase + AKV0 + (t & 1) * 65536;

        float sacc[8][4];
        #pragma unroll
        for (int i = 0; i < 8; i++)
            #pragma unroll
            for (int q = 0; q < 4; q++) sacc[i][q] = 0.f;

        #pragma unroll
        for (int ks = 0; ks < 8; ks++) {
            unsigned kh[8][2], kl[8][2];
            #pragma unroll
            for (int g = 0; g < 4; g++) {
                unsigned row = (unsigned)(g * 16 + b_row);
                unsigned ch = (unsigned)(ks * 2 + b_csel);
                unsigned addr = kvb + row * 256 + ((ch ^ (row & 7)) << 4);
                LDM4(kh[2*g][0], kh[2*g][1], kh[2*g+1][0], kh[2*g+1][1], addr);
                LDM4(kl[2*g][0], kl[2*g][1], kl[2*g+1][0], kl[2*g+1][1], addr + 16384);
            }
            unsigned qh0, qh1, qh2, qh3, ql0, ql1, ql2, ql3;
            {
                unsigned row = (unsigned)(wmQ + a_row);
                unsigned ch = (unsigned)(ks * 2 + a_csel);
                unsigned addr = sbase + AQH + row * 256 + ((ch ^ (row & 7)) << 4);
                LDM4(qh0, qh1, qh2, qh3, addr);
                LDM4(ql0, ql1, ql2, ql3, addr + 32768);
            }
            #pragma unroll
            for (int n8 = 0; n8 < 8; n8++) {
                MMA_BF16(sacc[n8][0], sacc[n8][1], sacc[n8][2], sacc[n8][3],
                         qh0, qh1, qh2, qh3, kh[n8][0], kh[n8][1]);
                MMA_BF16(sacc[n8][0], sacc[n8][1], sacc[n8][2], sacc[n8][3],
                         qh0, qh1, qh2, qh3, kl[n8][0], kl[n8][1]);
                MMA_BF16(sacc[n8][0], sacc[n8][1], sacc[n8][2], sacc[n8][3],
                         ql0, ql1, ql2, ql3, kh[n8][0], kh[n8][1]);
            }
        }

        #pragma unroll
        for (int n8 = 0; n8 < 8; n8++) {
            int jg0 = j0 + n8 * 8 + c_b;
            #pragma unroll
            for (int e = 0; e < 2; e++) {
                int jg = jg0 + e;
                float sv0 = sacc[n8][e] * scale;
                float sv1 = sacc[n8][2 + e] * scale;
                if (jg >= P_ && (jg - P_) > ig0) sv0 = -1e30f;
                if (jg >= P_ && (jg - P_) > ig1) sv1 = -1e30f;
                sacc[n8][e] = sv0;
                sacc[n8][2 + e] = sv1;
            }
        }

        float mx0 = -1e30f, mx1 = -1e30f;
        #pragma unroll
        for (int n8 = 0; n8 < 8; n8++) {
            mx0 = fmaxf(mx0, fmaxf(sacc[n8][0], sacc[n8][1]));
            mx1 = fmaxf(mx1, fmaxf(sacc[n8][2], sacc[n8][3]));
        }
        mx0 = fmaxf(mx0, __shfl_xor_sync(0xffffffffu, mx0, 1));
        mx0 = fmaxf(mx0, __shfl_xor_sync(0xffffffffu, mx0, 2));
        mx1 = fmaxf(mx1, __shfl_xor_sync(0xffffffffu, mx1, 1));
        mx1 = fmaxf(mx1, __shfl_xor_sync(0xffffffffu, mx1, 2));
        float mn0 = fmaxf(mrow0, mx0), mn1 = fmaxf(mrow1, mx1);
        float cor0 = __expf(mrow0 - mn0), cor1 = __expf(mrow1 - mn1);
        mrow0 = mn0; mrow1 = mn1;

        float sum0 = 0.f, sum1 = 0.f;
        #pragma unroll
        for (int n8 = 0; n8 < 8; n8++) {
            float p0 = __expf(sacc[n8][0] - mn0);
            float p1 = __expf(sacc[n8][1] - mn0);
            float p2 = __expf(sacc[n8][2] - mn1);
            float p3 = __expf(sacc[n8][3] - mn1);
            sum0 += p0 + p1; sum1 += p2 + p3;
            sacc[n8][0] = p0; sacc[n8][1] = p1; sacc[n8][2] = p2; sacc[n8][3] = p3;
        }
        sum0 += __shfl_xor_sync(0xffffffffu, sum0, 1);
        sum0 += __shfl_xor_sync(0xffffffffu, sum0, 2);
        sum1 += __shfl_xor_sync(0xffffffffu, sum1, 1);
        sum1 += __shfl_xor_sync(0xffffffffu, sum1, 2);
        lrow0 = lrow0 * cor0 + sum0;
        lrow1 = lrow1 * cor1 + sum1;

        unsigned pph[4][4], ppl[4][4];
        #pragma unroll
        for (int ks = 0; ks < 4; ks++) {
            SPLIT2X2(sacc[2*ks][0],   sacc[2*ks][1],   pph[ks][0], ppl[ks][0]);
            SPLIT2X2(sacc[2*ks][2],   sacc[2*ks][3],   pph[ks][1], ppl[ks][1]);
            SPLIT2X2(sacc[2*ks+1][0], sacc[2*ks+1][1], pph[ks][2], ppl[ks][2]);
            SPLIT2X2(sacc[2*ks+1][2], sacc[2*ks+1][3], pph[ks][3], ppl[ks][3]);
        }

        #pragma unroll
        for (int n8 = 0; n8 < 16; n8++) {
            oacc[n8][0] *= cor0; oacc[n8][1] *= cor0;
            oacc[n8][2] *= cor1; oacc[n8][3] *= cor1;
        }

        unsigned sVh = kvb + 32768;
        #pragma unroll
        for (int ks = 0; ks < 4; ks++) {
            #pragma unroll
            for (int half = 0; half < 2; half++) {
                unsigned vh[8][2], vl[8][2];
                unsigned krow = (unsigned)(ks * 16 + (lane & 15));
                unsigned chx = (unsigned)(lane >> 4);
                #pragma unroll
                for (int pi = 0; pi < 4; pi++) {
                    unsigned ch = (unsigned)((half * 4 + pi) * 2) + chx;
                    unsigned addr = sVh + krow * 256 + ((ch ^ (krow & 7)) << 4);
                    LDM4T(vh[2*pi][0], vh[2*pi][1], vh[2*pi+1][0], vh[2*pi+1][1], addr);
                    LDM4T(vl[2*pi][0], vl[2*pi][1], vl[2*pi+1][0], vl[2*pi+1][1], addr + 16384);
                }
                #pragma unroll
                for (int j = 0; j < 8; j++) {
                    int n8 = half * 8 + j;
                    MMA_BF16(oacc[n8][0], oacc[n8][1], oacc[n8][2], oacc[n8][3],
                             pph[ks][0], pph[ks][1], pph[ks][2], pph[ks][3],
                             vh[j][0], vh[j][1]);
                    MMA_BF16(oacc[n8][0], oacc[n8][1], oacc[n8][2], oacc[n8][3],
                             pph[ks][0], pph[ks][1], pph[ks][2], pph[ks][3],
                             vl[j][0], vl[j][1]);
                    MMA_BF16(oacc[n8][0], oacc[n8][1], oacc[n8][2], oacc[n8][3],
                             ppl[ks][0], ppl[ks][1], ppl[ks][2], ppl[ks][3],
                             vh[j][0], vh[j][1]);
                }
            }
        }
        __syncthreads();
    }

    float li0 = 1.0f / lrow0;
    float li1 = 1.0f / lrow1;
    size_t ro0 = ((size_t)(b * S_ + qbase + wmQ + r_b)) * D_ + h * DH_;
    size_t ro1 = ro0 + (size_t)8 * D_;
    #pragma unroll
    for (int n8 = 0; n8 < 16; n8++) {
        int c = n8 * 8 + c_b;
        unsigned hp, lp;
        SPLIT2X2(oacc[n8][0] * li0, oacc[n8][1] * li0, hp, lp);
        *(unsigned*)(g_A2h + ro0 + c) = hp;
        *(unsigned*)(g_A2l + ro0 + c) = lp;
        SPLIT2X2(oacc[n8][2] * li1, oacc[n8][3] * li1, hp, lp);
        *(unsigned*)(g_A2h + ro1 + c) = hp;
        *(unsigned*)(g_A2l + ro1 + c) = lp;
    }
}

// ---------------- launch ------------------------------------------------------
extern "C" void kernel_launch(void* const* d_in, const int* in_sizes, int n_in,
                              void* d_out, int out_size)
{
    const float* x    = (const float*)d_in[0];
    const float* vres = (const float*)d_in[1];
    const float* lng  = (const float*)d_in[2];
    const float* lnb  = (const float*)d_in[3];
    const float* wqkv = (const float*)d_in[4];
    const float* wout = (const float*)d_in[5];
    const float* bout = (const float*)d_in[6];
    const float* wmix = (const float*)d_in[7];
    const float* bmix = (const float*)d_in[8];
    const float* pmem = (const float*)d_in[9];
    float* out = (float*)d_out;

    cudaFuncSetAttribute(attn_kernel, cudaFuncAttributeMaxDynamicSharedMemorySize, ATTN_SMEM);
    cudaFuncSetAttribute(gemm_kernel<0>, cudaFuncAttributeMaxDynamicSharedMemorySize, GEMM_SMEM);
    cudaFuncSetAttribute(gemm_kernel<1>, cudaFuncAttributeMaxDynamicSharedMemorySize, GEMM_SMEM);

    ln_mix_kernel<<<BS_, 256>>>(x, lng, lnb, wmix, bmix);
    transconv_kernel<<<dim3(256, D_ / 32), 256>>>(wqkv, wout);
    pmem_kernel<<<256, 256>>>(pmem);
    gemm_kernel<0><<<dim3(3 * D_ / 256, BS_ / 128), 512, GEMM_SMEM>>>(vres, nullptr, nullptr);
    attn_kernel<<<dim3(S_ / 128, H_, B_), 256, ATTN_SMEM>>>();
    gemm_kernel<1><<<dim3(D_ / 256, BS_ / 128), 512, GEMM_SMEM>>>(nullptr, bout, out);
}

// round 14
// speedup vs baseline: 1.9347x; 1.9347x over previous
// Round 14: resubmission of round-13 source (round 13 hit the GB300 broker
// infra failure twice; never compiled/ran). Under test: single-pass fp16
// GEMMs (3x fewer MMAs), 2 CTAs/SM, bf16x3 attention unchanged.
#include <cuda_runtime.h>
#include <cuda_fp16.h>
#include <math.h>

#define B_   2
#define S_   2048
#define D_   2048
#define H_   16
#define DH_  128
#define P_   16
#define SP_  2064
#define BS_  4096
#define EPS_ 1e-5f

// ---------------- static scratch ----------------
__device__ __align__(16) unsigned short g_A1[BS_ * D_];       // xn fp16
__device__ __align__(16) unsigned short g_Bq[3 * D_ * D_];    // w_qkv^T fp16
__device__ __align__(16) unsigned short g_Bo[D_ * D_];        // w_out^T fp16
__device__ __align__(16) unsigned short g_A2[BS_ * D_];       // attn out fp16
__device__ float g_mix[BS_ * H_];
__device__ __align__(16) unsigned short g_qh[B_ * H_ * S_  * DH_];  // bf16 hi/lo (attention)
__device__ __align__(16) unsigned short g_ql[B_ * H_ * S_  * DH_];
__device__ __align__(16) unsigned short g_kh[B_ * H_ * SP_ * DH_];
__device__ __align__(16) unsigned short g_kl[B_ * H_ * SP_ * DH_];
__device__ __align__(16) unsigned short g_vh[B_ * H_ * SP_ * DH_];
__device__ __align__(16) unsigned short g_vl[B_ * H_ * SP_ * DH_];

// ---------------- helpers ----------------
__device__ __forceinline__ unsigned smem_u32(const void* p) {
    unsigned a;
    asm("{ .reg .u64 t; cvta.to.shared.u64 t, %1; cvt.u32.u64 %0, t; }" : "=r"(a) : "l"(p));
    return a;
}
__device__ __forceinline__ void cp16(unsigned s, const void* g) {
    asm volatile("cp.async.cg.shared.global [%0], [%1], 16;" :: "r"(s), "l"(g));
}
#define CP_COMMIT() asm volatile("cp.async.commit_group;" ::: "memory")
#define CP_WAIT1()  asm volatile("cp.async.wait_group 1;" ::: "memory")
#define CP_WAIT0()  asm volatile("cp.async.wait_group 0;" ::: "memory")

#define LDM4(d0, d1, d2, d3, addr) \
    asm volatile("ldmatrix.sync.aligned.m8n8.x4.shared.b16 {%0,%1,%2,%3}, [%4];" \
        : "=r"(d0), "=r"(d1), "=r"(d2), "=r"(d3) : "r"(addr))
#define LDM4T(d0, d1, d2, d3, addr) \
    asm volatile("ldmatrix.sync.aligned.m8n8.x4.trans.shared.b16 {%0,%1,%2,%3}, [%4];" \
        : "=r"(d0), "=r"(d1), "=r"(d2), "=r"(d3) : "r"(addr))

#define MMA_BF16(c0, c1, c2, c3, a0, a1, a2, a3, b0, b1) \
    asm volatile("mma.sync.aligned.m16n8k16.row.col.f32.bf16.bf16.f32 " \
        "{%0,%1,%2,%3}, {%4,%5,%6,%7}, {%8,%9}, {%0,%1,%2,%3};" \
        : "+f"(c0), "+f"(c1), "+f"(c2), "+f"(c3) \
        : "r"(a0), "r"(a1), "r"(a2), "r"(a3), "r"(b0), "r"(b1))

#define MMA_FP16(c0, c1, c2, c3, a0, a1, a2, a3, b0, b1) \
    asm volatile("mma.sync.aligned.m16n8k16.row.col.f32.f16.f16.f32 " \
        "{%0,%1,%2,%3}, {%4,%5,%6,%7}, {%8,%9}, {%0,%1,%2,%3};" \
        : "+f"(c0), "+f"(c1), "+f"(c2), "+f"(c3) \
        : "r"(a0), "r"(a1), "r"(a2), "r"(a3), "r"(b0), "r"(b1))

// bf16 split, RNE (attention path)
#define SPLIT2(v, hb, lb) do { \
    float _v = (v); \
    unsigned _u = __float_as_uint(_v); \
    hb = (_u + 0x7FFFu + ((_u >> 16) & 1u)) >> 16; \
    float _r = _v - __uint_as_float(hb << 16); \
    unsigned _w = __float_as_uint(_r); \
    lb = (_w + 0x7FFFu + ((_w >> 16) & 1u)) >> 16; \
} while (0)

#define SPLIT2X2(v0, v1, hpack, lpack) do { \
    float _a = (v0), _b = (v1); \
    asm("cvt.rn.bf16x2.f32 %0, %1, %2;" : "=r"(hpack) : "f"(_b), "f"(_a)); \
    float _r0 = _a - __uint_as_float((hpack) << 16); \
    float _r1 = _b - __uint_as_float((hpack) & 0xFFFF0000u); \
    asm("cvt.rn.bf16x2.f32 %0, %1, %2;" : "=r"(lpack) : "f"(_r1), "f"(_r0)); \
} while (0)

// fp16x2 pack: lo16 = fp16(v0), hi16 = fp16(v1)
#define PACK_F16X2(v0, v1, pack) \
    asm("cvt.rn.f16x2.f32 %0, %1, %2;" : "=r"(pack) : "f"(v1), "f"(v0))

// ---------------- kernel 1: LayerNorm + mix gate + fp16 out ------------------
__global__ __launch_bounds__(256) void ln_mix_kernel(
    const float* __restrict__ x, const float* __restrict__ lng,
    const float* __restrict__ lnb, const float* __restrict__ wmix,
    const float* __restrict__ bmix)
{
    int row = blockIdx.x;
    int tid = threadIdx.x;
    const float4* x4 = (const float4*)(x + (size_t)row * D_);
    float4 v0 = x4[tid];
    float4 v1 = x4[tid + 256];

    float s  = v0.x + v0.y + v0.z + v0.w + v1.x + v1.y + v1.z + v1.w;
    float s2 = v0.x*v0.x + v0.y*v0.y + v0.z*v0.z + v0.w*v0.w
             + v1.x*v1.x + v1.y*v1.y + v1.z*v1.z + v1.w*v1.w;
    #pragma unroll
    for (int o = 16; o; o >>= 1) {
        s  += __shfl_xor_sync(0xffffffffu, s,  o);
        s2 += __shfl_xor_sync(0xffffffffu, s2, o);
    }
    __shared__ float rs[8], rs2[8];
    int warp = tid >> 5, lane = tid & 31;
    if (lane == 0) { rs[warp] = s; rs2[warp] = s2; }
    __syncthreads();
    if (tid == 0) {
        float a = 0.f, b2 = 0.f;
        for (int w = 0; w < 8; w++) { a += rs[w]; b2 += rs2[w]; }
        rs[0] = a; rs2[0] = b2;
    }
    __syncthreads();
    float mu   = rs[0]  * (1.0f / D_);
    float var  = rs2[0] * (1.0f / D_) - mu * mu;
    float rstd = rsqrtf(var + EPS_);

    float xn[8];
    float xv[8] = {v0.x, v0.y, v0.z, v0.w, v1.x, v1.y, v1.z, v1.w};
    int jidx[8];
    #pragma unroll
    for (int e = 0; e < 8; e++) {
        int j = (e < 4) ? (4 * tid + e) : (1024 + 4 * tid + (e - 4));
        jidx[e] = j;
        xn[e] = (xv[e] - mu) * rstd * lng[j] + lnb[j];
    }
    unsigned p0, p1, p2, p3;
    PACK_F16X2(xn[0], xn[1], p0);
    PACK_F16X2(xn[2], xn[3], p1);
    PACK_F16X2(xn[4], xn[5], p2);
    PACK_F16X2(xn[6], xn[7], p3);
    size_t base = (size_t)row * D_;
    *(uint2*)(g_A1 + base + 4 * tid)        = make_uint2(p0, p1);
    *(uint2*)(g_A1 + base + 1024 + 4 * tid) = make_uint2(p2, p3);

    float acc[16];
    #pragma unroll
    for (int h = 0; h < 16; h++) acc[h] = 0.f;
    #pragma unroll
    for (int e = 0; e < 8; e++) {
        const float4* wm = (const float4*)(wmix + (size_t)jidx[e] * H_);
        float4 a0 = wm[0], a1 = wm[1], a2 = wm[2], a3 = wm[3];
        float xe = xn[e];
        acc[0]  += xe * a0.x; acc[1]  += xe * a0.y; acc[2]  += xe * a0.z; acc[3]  += xe * a0.w;
        acc[4]  += xe * a1.x; acc[5]  += xe * a1.y; acc[6]  += xe * a1.z; acc[7]  += xe * a1.w;
        acc[8]  += xe * a2.x; acc[9]  += xe * a2.y; acc[10] += xe * a2.z; acc[11] += xe * a2.w;
        acc[12] += xe * a3.x; acc[13] += xe * a3.y; acc[14] += xe * a3.z; acc[15] += xe * a3.w;
    }
    #pragma unroll
    for (int h = 0; h < 16; h++) {
        #pragma unroll
        for (int o = 16; o; o >>= 1) acc[h] += __shfl_xor_sync(0xffffffffu, acc[h], o);
    }
    __shared__ float wsum[8][16];
    if (lane == 0) {
        #pragma unroll
        for (int h = 0; h < 16; h++) wsum[warp][h] = acc[h];
    }
    __syncthreads();
    if (tid < 16) {
        float t = 0.f;
        #pragma unroll
        for (int w = 0; w < 8; w++) t += wsum[w][tid];
        t += bmix[tid];
        g_mix[(size_t)row * H_ + tid] = 1.0f / (1.0f + expf(-t));
    }
}

// ---------------- merged transpose + fp16 convert of both weights -----------
__global__ __launch_bounds__(256) void transconv_kernel(
    const float* __restrict__ wqkv, const float* __restrict__ wout)
{
    const float* src;
    unsigned short* dst;
    int Cols, bxe;
    int bx = blockIdx.x;
    if (bx < 192) { src = wqkv; dst = g_Bq; Cols = 3 * D_; bxe = bx; }
    else          { src = wout; dst = g_Bo; Cols = D_;     bxe = bx - 192; }
    const int Rows = D_;

    __shared__ float tile[32][33];
    int bcol = bxe * 32;
    int brow = blockIdx.y * 32;
    int tx = threadIdx.x & 31, ty = threadIdx.x >> 5;
    #pragma unroll
    for (int i = 0; i < 32; i += 8)
        tile[ty + i][tx] = src[(size_t)(brow + ty + i) * Cols + bcol + tx];
    __syncthreads();
    #pragma unroll
    for (int i = 0; i < 32; i += 8) {
        size_t o = (size_t)(bcol + ty + i) * Rows + brow + tx;
        dst[o] = __half_as_ushort(__float2half_rn(tile[tx][ty + i]));
    }
}

// ---------------- pmem prepend (bf16 split for attention) --------------------
__global__ __launch_bounds__(256) void pmem_kernel(const float* __restrict__ pmem)
{
    int i = blockIdx.x * 256 + threadIdx.x;
    int b = i >> 15;
    int rem = i & 32767;
    int h = rem >> 11;
    int jd = rem & 2047;
    int j = jd >> 7, d = jd & 127;
    size_t dst = (((size_t)(b * H_ + h)) * SP_ + j) * DH_ + d;
    unsigned kh, kl, vh, vl;
    SPLIT2(pmem[rem], kh, kl);
    SPLIT2(pmem[32768 + rem], vh, vl);
    g_kh[dst] = (unsigned short)kh;
    g_kl[dst] = (unsigned short)kl;
    g_vh[dst] = (unsigned short)vh;
    g_vl[dst] = (unsigned short)vl;
}

// ---------------- HMMA fp16 single-pass GEMM: 128x128, BK=64, 3-stage --------
#define BK_ 64
#define NCH (D_ / BK_)          // 32 chunks
#define STG 32768               // A 16K | B 16K
#define GEMM_SMEM (3 * STG + 1024)

#define LOAD_STAGE(st, k0) do { \
    unsigned _sp = sbase + (st) * STG; \
    _Pragma("unroll") \
    for (int _i = 0; _i < 4; _i++) { \
        int _ci = tid + _i * 256; \
        int _r = _ci >> 3, _c = _ci & 7; \
        unsigned _off = (unsigned)(_r * 128) + (((unsigned)_c ^ ((unsigned)_r & 7u)) << 4); \
        size_t _ga = (size_t)(m0 + _r) * D_ + (k0) + _c * 8; \
        size_t _gb = (size_t)(n0 + _r) * D_ + (k0) + _c * 8; \
        cp16(_sp + _off,         Am + _ga); \
        cp16(_sp + 16384 + _off, Bm + _gb); \
    } \
} while (0)

template <int MODE>
__global__ __launch_bounds__(256, 2) void gemm_kernel(
    const float* __restrict__ vres, const float* __restrict__ bout,
    float* __restrict__ Cout)
{
    extern __shared__ char dynsm[];
    unsigned braw = smem_u32(dynsm);
    unsigned sbase = (braw + 1023) & ~1023u;

    int tid = threadIdx.x;
    int lane = tid & 31, wid = tid >> 5;
    int warp_m = wid & 3, warp_n = wid >> 2;
    int m0 = blockIdx.y * 128, n0 = blockIdx.x * 128;
    int wm = warp_m * 32, wn = warp_n * 64;

    const unsigned short* Am = (MODE == 0) ? g_A1 : g_A2;
    const unsigned short* Bm = (MODE == 0) ? g_Bq : g_Bo;

    int t4 = lane >> 3, lr = lane & 7;
    int a_row  = ((t4 & 1) << 3) + lr;
    int a_csel = t4 >> 1;
    int b_row  = ((t4 >> 1) << 3) + lr;
    int b_csel = t4 & 1;

    float acc[2][8][4];
    #pragma unroll
    for (int i = 0; i < 2; i++)
        #pragma unroll
        for (int j = 0; j < 8; j++)
            #pragma unroll
            for (int q = 0; q < 4; q++) acc[i][j][q] = 0.f;

    LOAD_STAGE(0, 0); CP_COMMIT();
    LOAD_STAGE(1, BK_); CP_COMMIT();

    #pragma unroll 1
    for (int c = 0; c < NCH; c++) {
        if (c + 2 < NCH) CP_WAIT1(); else CP_WAIT0();
        __syncthreads();
        if (c + 2 < NCH) { LOAD_STAGE((c + 2) % 3, (c + 2) * BK_); CP_COMMIT(); }

        unsigned sp = sbase + (c % 3) * STG;
        unsigned sA = sp, sB = sp + 16384;

        #pragma unroll
        for (int ks = 0; ks < 4; ks++) {
            unsigned bb[8][2];
            #pragma unroll
            for (int np = 0; np < 4; np++) {
                unsigned row = (unsigned)(wn + np * 16 + b_row);
                unsigned ch = (unsigned)(ks * 2 + b_csel);
                unsigned off = row * 128 + ((ch ^ (row & 7)) << 4);
                LDM4(bb[2*np][0], bb[2*np][1], bb[2*np+1][0], bb[2*np+1][1], sB + off);
            }
            #pragma unroll
            for (int mt = 0; mt < 2; mt++) {
                unsigned a0, a1, a2, a3;
                unsigned row = (unsigned)(wm + mt * 16 + a_row);
                unsigned ch = (unsigned)(ks * 2 + a_csel);
                unsigned off = row * 128 + ((ch ^ (row & 7)) << 4);
                LDM4(a0, a1, a2, a3, sA + off);
                #pragma unroll
                for (int nt = 0; nt < 8; nt++) {
                    MMA_FP16(acc[mt][nt][0], acc[mt][nt][1], acc[mt][nt][2], acc[mt][nt][3],
                             a0, a1, a2, a3, bb[nt][0], bb[nt][1]);
                }
            }
        }
        __syncthreads();
    }

    // ---- epilogue ----
    #pragma unroll
    for (int mt = 0; mt < 2; mt++) {
        #pragma unroll
        for (int nt = 0; nt < 8; nt++) {
            int mrow0 = m0 + wm + mt * 16 + (lane >> 2);
            int n     = n0 + wn + nt * 8 + 2 * (lane & 3);
            #pragma unroll
            for (int half = 0; half < 2; half++) {
                int m = mrow0 + half * 8;
                float va = acc[mt][nt][2 * half];
                float vb = acc[mt][nt][2 * half + 1];
                int b = m >> 11, sg = m & 2047;
                if (MODE == 0) {
                    int seg = n >> 11;
                    int nn = n & 2047;
                    int hd = nn >> 7, d = nn & 127;
                    if (seg == 2) {
                        float mx = g_mix[(size_t)m * H_ + hd];
                        float2 vr = *(const float2*)(vres + (((size_t)(b * H_ + hd)) * S_ + sg) * DH_ + d);
                        float om = 1.0f - mx;
                        va = va * om + vr.x * mx;
                        vb = vb * om + vr.y * mx;
                    }
                    unsigned hp, lp;
                    SPLIT2X2(va, vb, hp, lp);
                    if (seg == 0) {
                        size_t idx = (((size_t)(b * H_ + hd)) * S_ + sg) * DH_ + d;
                        *(unsigned*)(g_qh + idx) = hp;
                        *(unsigned*)(g_ql + idx) = lp;
                    } else if (seg == 1) {
                        size_t idx = (((size_t)(b * H_ + hd)) * SP_ + P_ + sg) * DH_ + d;
                        *(unsigned*)(g_kh + idx) = hp;
                        *(unsigned*)(g_kl + idx) = lp;
                    } else {
                        size_t idx = (((size_t)(b * H_ + hd)) * SP_ + P_ + sg) * DH_ + d;
                        *(unsigned*)(g_vh + idx) = hp;
                        *(unsigned*)(g_vl + idx) = lp;
                    }
                } else {
                    *(float2*)(Cout + (size_t)m * D_ + n) =
                        make_float2(va + bout[n], vb + bout[n + 1]);
                }
            }
        }
    }
}

// ---------------- flash attention v3 (round-10; fp16 epilogue to g_A2) -------
#define AQH 0
#define AQL 32768
#define AKV0 65536
#define ATTN_SMEM (196608 + 1024)

#define LOAD_KV(bufi, j0v) do { \
    unsigned _kb = sbase + AKV0 + (bufi) * 65536; \
    size_t _gk = (size_t)bh * SP_; \
    _Pragma("unroll") \
    for (int _i = 0; _i < 4; _i++) { \
        int _ci = tid + _i * 256; \
        int _r = _ci >> 4, _c = _ci & 15; \
        int _jg = (j0v) + _r; if (_jg > SP_ - 1) _jg = SP_ - 1; \
        unsigned _d = _kb + (unsigned)(_r * 256) + (((unsigned)_c ^ ((unsigned)_r & 7u)) << 4); \
        size_t _go = (_gk + _jg) * DH_ + _c * 8; \
        cp16(_d,         g_kh + _go); \
        cp16(_d + 16384, g_kl + _go); \
        cp16(_d + 32768, g_vh + _go); \
        cp16(_d + 49152, g_vl + _go); \
    } \
} while (0)

__global__ __launch_bounds__(256, 1) void attn_kernel()
{
    extern __shared__ char dynsm2[];
    unsigned braw = smem_u32(dynsm2);
    unsigned sbase = (braw + 1023) & ~1023u;

    int tid = threadIdx.x;
    int lane = tid & 31, wid = tid >> 5;
    int qt = blockIdx.x, h = blockIdx.y, b = blockIdx.z;
    int bh = b * H_ + h;
    int qbase = qt * 128;

    {
        size_t gq = (size_t)bh * S_ + qbase;
        #pragma unroll
        for (int i = 0; i < 8; i++) {
            int ci = tid + i * 256;
            int r = ci >> 4, c = ci & 15;
            unsigned dst = sbase + AQH + (unsigned)(r * 256) + (((unsigned)c ^ ((unsigned)r & 7u)) << 4);
            cp16(dst,         g_qh + (gq + r) * DH_ + c * 8);
            cp16(dst + 32768, g_ql + (gq + r) * DH_ + c * 8);
        }
    }
    LOAD_KV(0, 0);
    CP_COMMIT();

    float oacc[16][4];
    #pragma unroll
    for (int i = 0; i < 16; i++)
        #pragma unroll
        for (int q = 0; q < 4; q++) oacc[i][q] = 0.f;
    float mrow0 = -INFINITY, mrow1 = -INFINITY, lrow0 = 0.f, lrow1 = 0.f;

    const float scale = 0.08838834764831845f;
    int ntiles = (P_ + qbase + 128 + 63) >> 6;

    int t4 = lane >> 3, lr = lane & 7;
    int a_row  = ((t4 & 1) << 3) + lr;
    int a_csel = t4 >> 1;
    int b_row  = ((t4 >> 1) << 3) + lr;
    int b_csel = t4 & 1;
    int r_b = lane >> 2, c_b = (lane & 3) * 2;
    int wmQ = wid * 16;
    int ig0 = qbase + wmQ + r_b;
    int ig1 = ig0 + 8;

    #pragma unroll 1
    for (int t = 0; t < ntiles; t++) {
        int j0 = t << 6;
        if (t + 1 < ntiles) { LOAD_KV((t + 1) & 1, (t + 1) * 64); CP_COMMIT(); CP_WAIT1(); }
        else CP_WAIT0();
        __syncthreads();

        unsigned kvb = sbase + AKV0 + (t & 1) * 65536;

        float sacc[8][4];
        #pragma unroll
        for (int i = 0; i < 8; i++)
            #pragma unroll
            for (int q = 0; q < 4; q++) sacc[i][q] = 0.f;

        #pragma unroll
        for (int ks = 0; ks < 8; ks++) {
            unsigned kh[8][2], kl[8][2];
            #pragma unroll
            for (int g = 0; g < 4; g++) {
                unsigned row = (unsigned)(g * 16 + b_row);
                unsigned ch = (unsigned)(ks * 2 + b_csel);
                unsigned addr = kvb + row * 256 + ((ch ^ (row & 7)) << 4);
                LDM4(kh[2*g][0], kh[2*g][1], kh[2*g+1][0], kh[2*g+1][1], addr);
                LDM4(kl[2*g][0], kl[2*g][1], kl[2*g+1][0], kl[2*g+1][1], addr + 16384);
            }
            unsigned qh0, qh1, qh2, qh3, ql0, ql1, ql2, ql3;
            {
                unsigned row = (unsigned)(wmQ + a_row);
                unsigned ch = (unsigned)(ks * 2 + a_csel);
                unsigned addr = sbase + AQH + row * 256 + ((ch ^ (row & 7)) << 4);
                LDM4(qh0, qh1, qh2, qh3, addr);
                LDM4(ql0, ql1, ql2, ql3, addr + 32768);
            }
            #pragma unroll
            for (int n8 = 0; n8 < 8; n8++) {
                MMA_BF16(sacc[n8][0], sacc[n8][1], sacc[n8][2], sacc[n8][3],
                         qh0, qh1, qh2, qh3, kh[n8][0], kh[n8][1]);
                MMA_BF16(sacc[n8][0], sacc[n8][1], sacc[n8][2], sacc[n8][3],
                         qh0, qh1, qh2, qh3, kl[n8][0], kl[n8][1]);
                MMA_BF16(sacc[n8][0], sacc[n8][1], sacc[n8][2], sacc[n8][3],
                         ql0, ql1, ql2, ql3, kh[n8][0], kh[n8][1]);
            }
        }

        #pragma unroll
        for (int n8 = 0; n8 < 8; n8++) {
            int jg0 = j0 + n8 * 8 + c_b;
            #pragma unroll
            for (int e = 0; e < 2; e++) {
                int jg = jg0 + e;
                float sv0 = sacc[n8][e] * scale;
                float sv1 = sacc[n8][2 + e] * scale;
                if (jg >= P_ && (jg - P_) > ig0) sv0 = -1e30f;
                if (jg >= P_ && (jg - P_) > ig1) sv1 = -1e30f;
                sacc[n8][e] = sv0;
                sacc[n8][2 + e] = sv1;
            }
        }

        float mx0 = -1e30f, mx1 = -1e30f;
        #pragma unroll
        for (int n8 = 0; n8 < 8; n8++) {
            mx0 = fmaxf(mx0, fmaxf(sacc[n8][0], sacc[n8][1]));
            mx1 = fmaxf(mx1, fmaxf(sacc[n8][2], sacc[n8][3]));
        }
        mx0 = fmaxf(mx0, __shfl_xor_sync(0xffffffffu, mx0, 1));
        mx0 = fmaxf(mx0, __shfl_xor_sync(0xffffffffu, mx0, 2));
        mx1 = fmaxf(mx1, __shfl_xor_sync(0xffffffffu, mx1, 1));
        mx1 = fmaxf(mx1, __shfl_xor_sync(0xffffffffu, mx1, 2));
        float mn0 = fmaxf(mrow0, mx0), mn1 = fmaxf(mrow1, mx1);
        float cor0 = __expf(mrow0 - mn0), cor1 = __expf(mrow1 - mn1);
        mrow0 = mn0; mrow1 = mn1;

        float sum0 = 0.f, sum1 = 0.f;
        #pragma unroll
        for (int n8 = 0; n8 < 8; n8++) {
            float p0 = __expf(sacc[n8][0] - mn0);
            float p1 = __expf(sacc[n8][1] - mn0);
            float p2 = __expf(sacc[n8][2] - mn1);
            float p3 = __expf(sacc[n8][3] - mn1);
            sum0 += p0 + p1; sum1 += p2 + p3;
            sacc[n8][0] = p0; sacc[n8][1] = p1; sacc[n8][2] = p2; sacc[n8][3] = p3;
        }
        sum0 += __shfl_xor_sync(0xffffffffu, sum0, 1);
        sum0 += __shfl_xor_sync(0xffffffffu, sum0, 2);
        sum1 += __shfl_xor_sync(0xffffffffu, sum1, 1);
        sum1 += __shfl_xor_sync(0xffffffffu, sum1, 2);
        lrow0 = lrow0 * cor0 + sum0;
        lrow1 = lrow1 * cor1 + sum1;

        unsigned pph[4][4], ppl[4][4];
        #pragma unroll
        for (int ks = 0; ks < 4; ks++) {
            SPLIT2X2(sacc[2*ks][0],   sacc[2*ks][1],   pph[ks][0], ppl[ks][0]);
            SPLIT2X2(sacc[2*ks][2],   sacc[2*ks][3],   pph[ks][1], ppl[ks][1]);
            SPLIT2X2(sacc[2*ks+1][0], sacc[2*ks+1][1], pph[ks][2], ppl[ks][2]);
            SPLIT2X2(sacc[2*ks+1][2], sacc[2*ks+1][3], pph[ks][3], ppl[ks][3]);
        }

        #pragma unroll
        for (int n8 = 0; n8 < 16; n8++) {
            oacc[n8][0] *= cor0; oacc[n8][1] *= cor0;
            oacc[n8][2] *= cor1; oacc[n8][3] *= cor1;
        }

        unsigned sVh = kvb + 32768;
        #pragma unroll
        for (int ks = 0; ks < 4; ks++) {
            #pragma unroll
            for (int half = 0; half < 2; half++) {
                unsigned vh[8][2], vl[8][2];
                unsigned krow = (unsigned)(ks * 16 + (lane & 15));
                unsigned chx = (unsigned)(lane >> 4);
                #pragma unroll
                for (int pi = 0; pi < 4; pi++) {
                    unsigned ch = (unsigned)((half * 4 + pi) * 2) + chx;
                    unsigned addr = sVh + krow * 256 + ((ch ^ (krow & 7)) << 4);
                    LDM4T(vh[2*pi][0], vh[2*pi][1], vh[2*pi+1][0], vh[2*pi+1][1], addr);
                    LDM4T(vl[2*pi][0], vl[2*pi][1], vl[2*pi+1][0], vl[2*pi+1][1], addr + 16384);
                }
                #pragma unroll
                for (int j = 0; j < 8; j++) {
                    int n8 = half * 8 + j;
                    MMA_BF16(oacc[n8][0], oacc[n8][1], oacc[n8][2], oacc[n8][3],
                             pph[ks][0], pph[ks][1], pph[ks][2], pph[ks][3],
                             vh[j][0], vh[j][1]);
                    MMA_BF16(oacc[n8][0], oacc[n8][1], oacc[n8][2], oacc[n8][3],
                             pph[ks][0], pph[ks][1], pph[ks][2], pph[ks][3],
                             vl[j][0], vl[j][1]);
                    MMA_BF16(oacc[n8][0], oacc[n8][1], oacc[n8][2], oacc[n8][3],
                             ppl[ks][0], ppl[ks][1], ppl[ks][2], ppl[ks][3],
                             vh[j][0], vh[j][1]);
                }
            }
        }
        __syncthreads();
    }

    float li0 = 1.0f / lrow0;
    float li1 = 1.0f / lrow1;
    size_t ro0 = ((size_t)(b * S_ + qbase + wmQ + r_b)) * D_ + h * DH_;
    size_t ro1 = ro0 + (size_t)8 * D_;
    #pragma unroll
    for (int n8 = 0; n8 < 16; n8++) {
        int c = n8 * 8 + c_b;
        unsigned p;
        PACK_F16X2(oacc[n8][0] * li0, oacc[n8][1] * li0, p);
        *(unsigned*)(g_A2 + ro0 + c) = p;
        PACK_F16X2(oacc[n8][2] * li1, oacc[n8][3] * li1, p);
        *(unsigned*)(g_A2 + ro1 + c) = p;
    }
}

// ---------------- launch ------------------------------------------------------
extern "C" void kernel_launch(void* const* d_in, const int* in_sizes, int n_in,
                              void* d_out, int out_size)
{
    const float* x    = (const float*)d_in[0];
    const float* vres = (const float*)d_in[1];
    const float* lng  = (const float*)d_in[2];
    const float* lnb  = (const float*)d_in[3];
    const float* wqkv = (const float*)d_in[4];
    const float* wout = (const float*)d_in[5];
    const float* bout = (const float*)d_in[6];
    const float* wmix = (const float*)d_in[7];
    const float* bmix = (const float*)d_in[8];
    const float* pmem = (const float*)d_in[9];
    float* out = (float*)d_out;

    cudaFuncSetAttribute(attn_kernel, cudaFuncAttributeMaxDynamicSharedMemorySize, ATTN_SMEM);
    cudaFuncSetAttribute(gemm_kernel<0>, cudaFuncAttributeMaxDynamicSharedMemorySize, GEMM_SMEM);
    cudaFuncSetAttribute(gemm_kernel<1>, cudaFuncAttributeMaxDynamicSharedMemorySize, GEMM_SMEM);

    ln_mix_kernel<<<BS_, 256>>>(x, lng, lnb, wmix, bmix);
    transconv_kernel<<<dim3(256, D_ / 32), 256>>>(wqkv, wout);
    pmem_kernel<<<256, 256>>>(pmem);
    gemm_kernel<0><<<dim3(3 * D_ / 128, BS_ / 128), 256, GEMM_SMEM>>>(vres, nullptr, nullptr);
    attn_kernel<<<dim3(S_ / 128, H_, B_), 256, ATTN_SMEM>>>();
    gemm_kernel<1><<<dim3(D_ / 128, BS_ / 128), 256, GEMM_SMEM>>>(nullptr, bout, out);
}

// round 16
// speedup vs baseline: 2.3809x; 1.2306x over previous
// Round 16: resubmission of round-15 source (round 15 hit the GB300 broker
// infra failure twice; never compiled/ran). Under test: full-fp16 attention
// (1 MMA per matmul), fp16 q/k/v storage, 2 CTAs/SM attention.
#include <cuda_runtime.h>
#include <cuda_fp16.h>
#include <math.h>

#define B_   2
#define S_   2048
#define D_   2048
#define H_   16
#define DH_  128
#define P_   16
#define SP_  2064
#define BS_  4096
#define EPS_ 1e-5f

// ---------------- static scratch (all activation tensors fp16) ---------------
__device__ __align__(16) unsigned short g_A1[BS_ * D_];       // xn fp16
__device__ __align__(16) unsigned short g_Bq[3 * D_ * D_];    // w_qkv^T fp16
__device__ __align__(16) unsigned short g_Bo[D_ * D_];        // w_out^T fp16
__device__ __align__(16) unsigned short g_A2[BS_ * D_];       // attn out fp16
__device__ float g_mix[BS_ * H_];
__device__ __align__(16) unsigned short g_q[B_ * H_ * S_  * DH_];
__device__ __align__(16) unsigned short g_k[B_ * H_ * SP_ * DH_];
__device__ __align__(16) unsigned short g_v[B_ * H_ * SP_ * DH_];

// ---------------- helpers ----------------
__device__ __forceinline__ unsigned smem_u32(const void* p) {
    unsigned a;
    asm("{ .reg .u64 t; cvta.to.shared.u64 t, %1; cvt.u32.u64 %0, t; }" : "=r"(a) : "l"(p));
    return a;
}
__device__ __forceinline__ void cp16(unsigned s, const void* g) {
    asm volatile("cp.async.cg.shared.global [%0], [%1], 16;" :: "r"(s), "l"(g));
}
#define CP_COMMIT() asm volatile("cp.async.commit_group;" ::: "memory")
#define CP_WAIT1()  asm volatile("cp.async.wait_group 1;" ::: "memory")
#define CP_WAIT0()  asm volatile("cp.async.wait_group 0;" ::: "memory")

#define LDM4(d0, d1, d2, d3, addr) \
    asm volatile("ldmatrix.sync.aligned.m8n8.x4.shared.b16 {%0,%1,%2,%3}, [%4];" \
        : "=r"(d0), "=r"(d1), "=r"(d2), "=r"(d3) : "r"(addr))
#define LDM4T(d0, d1, d2, d3, addr) \
    asm volatile("ldmatrix.sync.aligned.m8n8.x4.trans.shared.b16 {%0,%1,%2,%3}, [%4];" \
        : "=r"(d0), "=r"(d1), "=r"(d2), "=r"(d3) : "r"(addr))

#define MMA_FP16(c0, c1, c2, c3, a0, a1, a2, a3, b0, b1) \
    asm volatile("mma.sync.aligned.m16n8k16.row.col.f32.f16.f16.f32 " \
        "{%0,%1,%2,%3}, {%4,%5,%6,%7}, {%8,%9}, {%0,%1,%2,%3};" \
        : "+f"(c0), "+f"(c1), "+f"(c2), "+f"(c3) \
        : "r"(a0), "r"(a1), "r"(a2), "r"(a3), "r"(b0), "r"(b1))

// fp16x2 pack: lo16 = fp16(v0), hi16 = fp16(v1)
#define PACK_F16X2(v0, v1, pack) \
    asm("cvt.rn.f16x2.f32 %0, %1, %2;" : "=r"(pack) : "f"(v1), "f"(v0))

// ---------------- kernel 1: LayerNorm + mix gate + fp16 out ------------------
__global__ __launch_bounds__(256) void ln_mix_kernel(
    const float* __restrict__ x, const float* __restrict__ lng,
    const float* __restrict__ lnb, const float* __restrict__ wmix,
    const float* __restrict__ bmix)
{
    int row = blockIdx.x;
    int tid = threadIdx.x;
    const float4* x4 = (const float4*)(x + (size_t)row * D_);
    float4 v0 = x4[tid];
    float4 v1 = x4[tid + 256];

    float s  = v0.x + v0.y + v0.z + v0.w + v1.x + v1.y + v1.z + v1.w;
    float s2 = v0.x*v0.x + v0.y*v0.y + v0.z*v0.z + v0.w*v0.w
             + v1.x*v1.x + v1.y*v1.y + v1.z*v1.z + v1.w*v1.w;
    #pragma unroll
    for (int o = 16; o; o >>= 1) {
        s  += __shfl_xor_sync(0xffffffffu, s,  o);
        s2 += __shfl_xor_sync(0xffffffffu, s2, o);
    }
    __shared__ float rs[8], rs2[8];
    int warp = tid >> 5, lane = tid & 31;
    if (lane == 0) { rs[warp] = s; rs2[warp] = s2; }
    __syncthreads();
    if (tid == 0) {
        float a = 0.f, b2 = 0.f;
        for (int w = 0; w < 8; w++) { a += rs[w]; b2 += rs2[w]; }
        rs[0] = a; rs2[0] = b2;
    }
    __syncthreads();
    float mu   = rs[0]  * (1.0f / D_);
    float var  = rs2[0] * (1.0f / D_) - mu * mu;
    float rstd = rsqrtf(var + EPS_);

    float xn[8];
    float xv[8] = {v0.x, v0.y, v0.z, v0.w, v1.x, v1.y, v1.z, v1.w};
    int jidx[8];
    #pragma unroll
    for (int e = 0; e < 8; e++) {
        int j = (e < 4) ? (4 * tid + e) : (1024 + 4 * tid + (e - 4));
        jidx[e] = j;
        xn[e] = (xv[e] - mu) * rstd * lng[j] + lnb[j];
    }
    unsigned p0, p1, p2, p3;
    PACK_F16X2(xn[0], xn[1], p0);
    PACK_F16X2(xn[2], xn[3], p1);
    PACK_F16X2(xn[4], xn[5], p2);
    PACK_F16X2(xn[6], xn[7], p3);
    size_t base = (size_t)row * D_;
    *(uint2*)(g_A1 + base + 4 * tid)        = make_uint2(p0, p1);
    *(uint2*)(g_A1 + base + 1024 + 4 * tid) = make_uint2(p2, p3);

    float acc[16];
    #pragma unroll
    for (int h = 0; h < 16; h++) acc[h] = 0.f;
    #pragma unroll
    for (int e = 0; e < 8; e++) {
        const float4* wm = (const float4*)(wmix + (size_t)jidx[e] * H_);
        float4 a0 = wm[0], a1 = wm[1], a2 = wm[2], a3 = wm[3];
        float xe = xn[e];
        acc[0]  += xe * a0.x; acc[1]  += xe * a0.y; acc[2]  += xe * a0.z; acc[3]  += xe * a0.w;
        acc[4]  += xe * a1.x; acc[5]  += xe * a1.y; acc[6]  += xe * a1.z; acc[7]  += xe * a1.w;
        acc[8]  += xe * a2.x; acc[9]  += xe * a2.y; acc[10] += xe * a2.z; acc[11] += xe * a2.w;
        acc[12] += xe * a3.x; acc[13] += xe * a3.y; acc[14] += xe * a3.z; acc[15] += xe * a3.w;
    }
    #pragma unroll
    for (int h = 0; h < 16; h++) {
        #pragma unroll
        for (int o = 16; o; o >>= 1) acc[h] += __shfl_xor_sync(0xffffffffu, acc[h], o);
    }
    __shared__ float wsum[8][16];
    if (lane == 0) {
        #pragma unroll
        for (int h = 0; h < 16; h++) wsum[warp][h] = acc[h];
    }
    __syncthreads();
    if (tid < 16) {
        float t = 0.f;
        #pragma unroll
        for (int w = 0; w < 8; w++) t += wsum[w][tid];
        t += bmix[tid];
        g_mix[(size_t)row * H_ + tid] = 1.0f / (1.0f + expf(-t));
    }
}

// ---------------- merged transpose + fp16 convert of both weights -----------
__global__ __launch_bounds__(256) void transconv_kernel(
    const float* __restrict__ wqkv, const float* __restrict__ wout)
{
    const float* src;
    unsigned short* dst;
    int Cols, bxe;
    int bx = blockIdx.x;
    if (bx < 192) { src = wqkv; dst = g_Bq; Cols = 3 * D_; bxe = bx; }
    else          { src = wout; dst = g_Bo; Cols = D_;     bxe = bx - 192; }
    const int Rows = D_;

    __shared__ float tile[32][33];
    int bcol = bxe * 32;
    int brow = blockIdx.y * 32;
    int tx = threadIdx.x & 31, ty = threadIdx.x >> 5;
    #pragma unroll
    for (int i = 0; i < 32; i += 8)
        tile[ty + i][tx] = src[(size_t)(brow + ty + i) * Cols + bcol + tx];
    __syncthreads();
    #pragma unroll
    for (int i = 0; i < 32; i += 8) {
        size_t o = (size_t)(bcol + ty + i) * Rows + brow + tx;
        dst[o] = __half_as_ushort(__float2half_rn(tile[tx][ty + i]));
    }
}

// ---------------- pmem prepend (fp16) ----------------
__global__ __launch_bounds__(256) void pmem_kernel(const float* __restrict__ pmem)
{
    int i = blockIdx.x * 256 + threadIdx.x;
    int b = i >> 15;
    int rem = i & 32767;
    int h = rem >> 11;
    int jd = rem & 2047;
    int j = jd >> 7, d = jd & 127;
    size_t dst = (((size_t)(b * H_ + h)) * SP_ + j) * DH_ + d;
    g_k[dst] = __half_as_ushort(__float2half_rn(pmem[rem]));
    g_v[dst] = __half_as_ushort(__float2half_rn(pmem[32768 + rem]));
}

// ---------------- HMMA fp16 single-pass GEMM: 128x128, BK=64, 3-stage --------
#define BK_ 64
#define NCH (D_ / BK_)          // 32 chunks
#define STG 32768               // A 16K | B 16K
#define GEMM_SMEM (3 * STG + 1024)

#define LOAD_STAGE(st, k0) do { \
    unsigned _sp = sbase + (st) * STG; \
    _Pragma("unroll") \
    for (int _i = 0; _i < 4; _i++) { \
        int _ci = tid + _i * 256; \
        int _r = _ci >> 3, _c = _ci & 7; \
        unsigned _off = (unsigned)(_r * 128) + (((unsigned)_c ^ ((unsigned)_r & 7u)) << 4); \
        size_t _ga = (size_t)(m0 + _r) * D_ + (k0) + _c * 8; \
        size_t _gb = (size_t)(n0 + _r) * D_ + (k0) + _c * 8; \
        cp16(_sp + _off,         Am + _ga); \
        cp16(_sp + 16384 + _off, Bm + _gb); \
    } \
} while (0)

template <int MODE>
__global__ __launch_bounds__(256, 2) void gemm_kernel(
    const float* __restrict__ vres, const float* __restrict__ bout,
    float* __restrict__ Cout)
{
    extern __shared__ char dynsm[];
    unsigned braw = smem_u32(dynsm);
    unsigned sbase = (braw + 1023) & ~1023u;

    int tid = threadIdx.x;
    int lane = tid & 31, wid = tid >> 5;
    int warp_m = wid & 3, warp_n = wid >> 2;
    int m0 = blockIdx.y * 128, n0 = blockIdx.x * 128;
    int wm = warp_m * 32, wn = warp_n * 64;

    const unsigned short* Am = (MODE == 0) ? g_A1 : g_A2;
    const unsigned short* Bm = (MODE == 0) ? g_Bq : g_Bo;

    int t4 = lane >> 3, lr = lane & 7;
    int a_row  = ((t4 & 1) << 3) + lr;
    int a_csel = t4 >> 1;
    int b_row  = ((t4 >> 1) << 3) + lr;
    int b_csel = t4 & 1;

    float acc[2][8][4];
    #pragma unroll
    for (int i = 0; i < 2; i++)
        #pragma unroll
        for (int j = 0; j < 8; j++)
            #pragma unroll
            for (int q = 0; q < 4; q++) acc[i][j][q] = 0.f;

    LOAD_STAGE(0, 0); CP_COMMIT();
    LOAD_STAGE(1, BK_); CP_COMMIT();

    #pragma unroll 1
    for (int c = 0; c < NCH; c++) {
        if (c + 2 < NCH) CP_WAIT1(); else CP_WAIT0();
        __syncthreads();
        if (c + 2 < NCH) { LOAD_STAGE((c + 2) % 3, (c + 2) * BK_); CP_COMMIT(); }

        unsigned sp = sbase + (c % 3) * STG;
        unsigned sA = sp, sB = sp + 16384;

        #pragma unroll
        for (int ks = 0; ks < 4; ks++) {
            unsigned bb[8][2];
            #pragma unroll
            for (int np = 0; np < 4; np++) {
                unsigned row = (unsigned)(wn + np * 16 + b_row);
                unsigned ch = (unsigned)(ks * 2 + b_csel);
                unsigned off = row * 128 + ((ch ^ (row & 7)) << 4);
                LDM4(bb[2*np][0], bb[2*np][1], bb[2*np+1][0], bb[2*np+1][1], sB + off);
            }
            #pragma unroll
            for (int mt = 0; mt < 2; mt++) {
                unsigned a0, a1, a2, a3;
                unsigned row = (unsigned)(wm + mt * 16 + a_row);
                unsigned ch = (unsigned)(ks * 2 + a_csel);
                unsigned off = row * 128 + ((ch ^ (row & 7)) << 4);
                LDM4(a0, a1, a2, a3, sA + off);
                #pragma unroll
                for (int nt = 0; nt < 8; nt++) {
                    MMA_FP16(acc[mt][nt][0], acc[mt][nt][1], acc[mt][nt][2], acc[mt][nt][3],
                             a0, a1, a2, a3, bb[nt][0], bb[nt][1]);
                }
            }
        }
        __syncthreads();
    }

    // ---- epilogue ----
    #pragma unroll
    for (int mt = 0; mt < 2; mt++) {
        #pragma unroll
        for (int nt = 0; nt < 8; nt++) {
            int mrow0 = m0 + wm + mt * 16 + (lane >> 2);
            int n     = n0 + wn + nt * 8 + 2 * (lane & 3);
            #pragma unroll
            for (int half = 0; half < 2; half++) {
                int m = mrow0 + half * 8;
                float va = acc[mt][nt][2 * half];
                float vb = acc[mt][nt][2 * half + 1];
                int b = m >> 11, sg = m & 2047;
                if (MODE == 0) {
                    int seg = n >> 11;
                    int nn = n & 2047;
                    int hd = nn >> 7, d = nn & 127;
                    if (seg == 2) {
                        float mx = g_mix[(size_t)m * H_ + hd];
                        float2 vr = *(const float2*)(vres + (((size_t)(b * H_ + hd)) * S_ + sg) * DH_ + d);
                        float om = 1.0f - mx;
                        va = va * om + vr.x * mx;
                        vb = vb * om + vr.y * mx;
                    }
                    unsigned p;
                    PACK_F16X2(va, vb, p);
                    if (seg == 0) {
                        *(unsigned*)(g_q + (((size_t)(b * H_ + hd)) * S_ + sg) * DH_ + d) = p;
                    } else if (seg == 1) {
                        *(unsigned*)(g_k + (((size_t)(b * H_ + hd)) * SP_ + P_ + sg) * DH_ + d) = p;
                    } else {
                        *(unsigned*)(g_v + (((size_t)(b * H_ + hd)) * SP_ + P_ + sg) * DH_ + d) = p;
                    }
                } else {
                    *(float2*)(Cout + (size_t)m * D_ + n) =
                        make_float2(va + bout[n], vb + bout[n + 1]);
                }
            }
        }
    }
}

// ---------------- flash attention v4: full fp16, Q128, register P ------------
#define AQ 0
#define AKV0 32768                 // 2 bufs x 32KB {K 16K | V 16K}
#define ATTN_SMEM (32768 + 2 * 32768 + 1024)

#define LOAD_KV(bufi, j0v) do { \
    unsigned _kb = sbase + AKV0 + (bufi) * 32768; \
    size_t _gk = (size_t)bh * SP_; \
    _Pragma("unroll") \
    for (int _i = 0; _i < 4; _i++) { \
        int _ci = tid + _i * 256; \
        int _r = _ci >> 4, _c = _ci & 15; \
        int _jg = (j0v) + _r; if (_jg > SP_ - 1) _jg = SP_ - 1; \
        unsigned _d = _kb + (unsigned)(_r * 256) + (((unsigned)_c ^ ((unsigned)_r & 7u)) << 4); \
        size_t _go = (_gk + _jg) * DH_ + _c * 8; \
        cp16(_d,         g_k + _go); \
        cp16(_d + 16384, g_v + _go); \
    } \
} while (0)

__global__ __launch_bounds__(256, 2) void attn_kernel()
{
    extern __shared__ char dynsm2[];
    unsigned braw = smem_u32(dynsm2);
    unsigned sbase = (braw + 1023) & ~1023u;

    int tid = threadIdx.x;
    int lane = tid & 31, wid = tid >> 5;
    int qt = blockIdx.x, h = blockIdx.y, b = blockIdx.z;
    int bh = b * H_ + h;
    int qbase = qt * 128;

    {
        size_t gq = (size_t)bh * S_ + qbase;
        #pragma unroll
        for (int i = 0; i < 8; i++) {
            int ci = tid + i * 256;
            int r = ci >> 4, c = ci & 15;
            unsigned dst = sbase + AQ + (unsigned)(r * 256) + (((unsigned)c ^ ((unsigned)r & 7u)) << 4);
            cp16(dst, g_q + (gq + r) * DH_ + c * 8);
        }
    }
    LOAD_KV(0, 0);
    CP_COMMIT();

    float oacc[16][4];
    #pragma unroll
    for (int i = 0; i < 16; i++)
        #pragma unroll
        for (int q = 0; q < 4; q++) oacc[i][q] = 0.f;
    float mrow0 = -INFINITY, mrow1 = -INFINITY, lrow0 = 0.f, lrow1 = 0.f;

    const float scale = 0.08838834764831845f;
    int ntiles = (P_ + qbase + 128 + 63) >> 6;

    int t4 = lane >> 3, lr = lane & 7;
    int a_row  = ((t4 & 1) << 3) + lr;
    int a_csel = t4 >> 1;
    int b_row  = ((t4 >> 1) << 3) + lr;
    int b_csel = t4 & 1;
    int r_b = lane >> 2, c_b = (lane & 3) * 2;
    int wmQ = wid * 16;
    int ig0 = qbase + wmQ + r_b;
    int ig1 = ig0 + 8;

    #pragma unroll 1
    for (int t = 0; t < ntiles; t++) {
        int j0 = t << 6;
        if (t + 1 < ntiles) { LOAD_KV((t + 1) & 1, (t + 1) * 64); CP_COMMIT(); CP_WAIT1(); }
        else CP_WAIT0();
        __syncthreads();

        unsigned kvb = sbase + AKV0 + (t & 1) * 32768;

        float sacc[8][4];
        #pragma unroll
        for (int i = 0; i < 8; i++)
            #pragma unroll
            for (int q = 0; q < 4; q++) sacc[i][q] = 0.f;

        #pragma unroll
        for (int ks = 0; ks < 8; ks++) {
            unsigned kk[8][2];
            #pragma unroll
            for (int g = 0; g < 4; g++) {
                unsigned row = (unsigned)(g * 16 + b_row);
                unsigned ch = (unsigned)(ks * 2 + b_csel);
                unsigned addr = kvb + row * 256 + ((ch ^ (row & 7)) << 4);
                LDM4(kk[2*g][0], kk[2*g][1], kk[2*g+1][0], kk[2*g+1][1], addr);
            }
            unsigned q0, q1, q2, q3;
            {
                unsigned row = (unsigned)(wmQ + a_row);
                unsigned ch = (unsigned)(ks * 2 + a_csel);
                unsigned addr = sbase + AQ + row * 256 + ((ch ^ (row & 7)) << 4);
                LDM4(q0, q1, q2, q3, addr);
            }
            #pragma unroll
            for (int n8 = 0; n8 < 8; n8++) {
                MMA_FP16(sacc[n8][0], sacc[n8][1], sacc[n8][2], sacc[n8][3],
                         q0, q1, q2, q3, kk[n8][0], kk[n8][1]);
            }
        }

        #pragma unroll
        for (int n8 = 0; n8 < 8; n8++) {
            int jg0 = j0 + n8 * 8 + c_b;
            #pragma unroll
            for (int e = 0; e < 2; e++) {
                int jg = jg0 + e;
                float sv0 = sacc[n8][e] * scale;
                float sv1 = sacc[n8][2 + e] * scale;
                if (jg >= P_ && (jg - P_) > ig0) sv0 = -1e30f;
                if (jg >= P_ && (jg - P_) > ig1) sv1 = -1e30f;
                sacc[n8][e] = sv0;
                sacc[n8][2 + e] = sv1;
            }
        }

        float mx0 = -1e30f, mx1 = -1e30f;
        #pragma unroll
        for (int n8 = 0; n8 < 8; n8++) {
            mx0 = fmaxf(mx0, fmaxf(sacc[n8][0], sacc[n8][1]));
            mx1 = fmaxf(mx1, fmaxf(sacc[n8][2], sacc[n8][3]));
        }
        mx0 = fmaxf(mx0, __shfl_xor_sync(0xffffffffu, mx0, 1));
        mx0 = fmaxf(mx0, __shfl_xor_sync(0xffffffffu, mx0, 2));
        mx1 = fmaxf(mx1, __shfl_xor_sync(0xffffffffu, mx1, 1));
        mx1 = fmaxf(mx1, __shfl_xor_sync(0xffffffffu, mx1, 2));
        float mn0 = fmaxf(mrow0, mx0), mn1 = fmaxf(mrow1, mx1);
        float cor0 = __expf(mrow0 - mn0), cor1 = __expf(mrow1 - mn1);
        mrow0 = mn0; mrow1 = mn1;

        float sum0 = 0.f, sum1 = 0.f;
        #pragma unroll
        for (int n8 = 0; n8 < 8; n8++) {
            float p0 = __expf(sacc[n8][0] - mn0);
            float p1 = __expf(sacc[n8][1] - mn0);
            float p2 = __expf(sacc[n8][2] - mn1);
            float p3 = __expf(sacc[n8][3] - mn1);
            sum0 += p0 + p1; sum1 += p2 + p3;
            sacc[n8][0] = p0; sacc[n8][1] = p1; sacc[n8][2] = p2; sacc[n8][3] = p3;
        }
        sum0 += __shfl_xor_sync(0xffffffffu, sum0, 1);
        sum0 += __shfl_xor_sync(0xffffffffu, sum0, 2);
        sum1 += __shfl_xor_sync(0xffffffffu, sum1, 1);
        sum1 += __shfl_xor_sync(0xffffffffu, sum1, 2);
        lrow0 = lrow0 * cor0 + sum0;
        lrow1 = lrow1 * cor1 + sum1;

        // pack P fp16 into A-operand fragments (C-frag == A-frag layout)
        unsigned pp[4][4];
        #pragma unroll
        for (int ks = 0; ks < 4; ks++) {
            PACK_F16X2(sacc[2*ks][0],   sacc[2*ks][1],   pp[ks][0]);
            PACK_F16X2(sacc[2*ks][2],   sacc[2*ks][3],   pp[ks][1]);
            PACK_F16X2(sacc[2*ks+1][0], sacc[2*ks+1][1], pp[ks][2]);
            PACK_F16X2(sacc[2*ks+1][2], sacc[2*ks+1][3], pp[ks][3]);
        }

        #pragma unroll
        for (int n8 = 0; n8 < 16; n8++) {
            oacc[n8][0] *= cor0; oacc[n8][1] *= cor0;
            oacc[n8][2] *= cor1; oacc[n8][3] *= cor1;
        }

        unsigned sV = kvb + 16384;
        #pragma unroll
        for (int ks = 0; ks < 4; ks++) {
            #pragma unroll
            for (int half = 0; half < 2; half++) {
                unsigned vv[8][2];
                unsigned krow = (unsigned)(ks * 16 + (lane & 15));
                unsigned chx = (unsigned)(lane >> 4);
                #pragma unroll
                for (int pi = 0; pi < 4; pi++) {
                    unsigned ch = (unsigned)((half * 4 + pi) * 2) + chx;
                    unsigned addr = sV + krow * 256 + ((ch ^ (krow & 7)) << 4);
                    LDM4T(vv[2*pi][0], vv[2*pi][1], vv[2*pi+1][0], vv[2*pi+1][1], addr);
                }
                #pragma unroll
                for (int j = 0; j < 8; j++) {
                    int n8 = half * 8 + j;
                    MMA_FP16(oacc[n8][0], oacc[n8][1], oacc[n8][2], oacc[n8][3],
                             pp[ks][0], pp[ks][1], pp[ks][2], pp[ks][3],
                             vv[j][0], vv[j][1]);
                }
            }
        }
        __syncthreads();
    }

    float li0 = 1.0f / lrow0;
    float li1 = 1.0f / lrow1;
    size_t ro0 = ((size_t)(b * S_ + qbase + wmQ + r_b)) * D_ + h * DH_;
    size_t ro1 = ro0 + (size_t)8 * D_;
    #pragma unroll
    for (int n8 = 0; n8 < 16; n8++) {
        int c = n8 * 8 + c_b;
        unsigned p;
        PACK_F16X2(oacc[n8][0] * li0, oacc[n8][1] * li0, p);
        *(unsigned*)(g_A2 + ro0 + c) = p;
        PACK_F16X2(oacc[n8][2] * li1, oacc[n8][3] * li1, p);
        *(unsigned*)(g_A2 + ro1 + c) = p;
    }
}

// ---------------- launch ------------------------------------------------------
extern "C" void kernel_launch(void* const* d_in, const int* in_sizes, int n_in,
                              void* d_out, int out_size)
{
    const float* x    = (const float*)d_in[0];
    const float* vres = (const float*)d_in[1];
    const float* lng  = (const float*)d_in[2];
    const float* lnb  = (const float*)d_in[3];
    const float* wqkv = (const float*)d_in[4];
    const float* wout = (const float*)d_in[5];
    const float* bout = (const float*)d_in[6];
    const float* wmix = (const float*)d_in[7];
    const float* bmix = (const float*)d_in[8];
    const float* pmem = (const float*)d_in[9];
    float* out = (float*)d_out;

    cudaFuncSetAttribute(attn_kernel, cudaFuncAttributeMaxDynamicSharedMemorySize, ATTN_SMEM);
    cudaFuncSetAttribute(gemm_kernel<0>, cudaFuncAttributeMaxDynamicSharedMemorySize, GEMM_SMEM);
    cudaFuncSetAttribute(gemm_kernel<1>, cudaFuncAttributeMaxDynamicSharedMemorySize, GEMM_SMEM);

    ln_mix_kernel<<<BS_, 256>>>(x, lng, lnb, wmix, bmix);
    transconv_kernel<<<dim3(256, D_ / 32), 256>>>(wqkv, wout);
    pmem_kernel<<<256, 256>>>(pmem);
    gemm_kernel<0><<<dim3(3 * D_ / 128, BS_ / 128), 256, GEMM_SMEM>>>(vres, nullptr, nullptr);
    attn_kernel<<<dim3(S_ / 128, H_, B_), 256, ATTN_SMEM>>>();
    gemm_kernel<1><<<dim3(D_ / 128, BS_ / 128), 256, GEMM_SMEM>>>(nullptr, bout, out);
}